// round 2
// baseline (speedup 1.0000x reference)
#include <cuda_runtime.h>
#include <math.h>

// Problem constants
#define HH 128
#define WW 128
#define HW 16384
#define NB 2
#define HEADS 4
#define CIN3 384
#define NSEG 16

// ---------------- scratch (static device arrays; no allocation) ----------------
__device__ float g_W1t[128 * 384];            // qkv weight, [k][m]
__device__ float g_W2t[384 * 9 * 384];        // dw weight, [ci][tap][co]
__device__ float g_W3t[128 * 128];            // po weight, [k][m]
__device__ float g_Y1[(size_t)NB * 384 * HW]; // after qkv 1x1
__device__ float g_Y2[(size_t)NB * 384 * HW]; // after dw 3x3
__device__ float g_Gp[NSEG * NB * HEADS * 32 * 32]; // gram partials per segment
__device__ float g_SQp[NSEG * NB * HEADS * 32];
__device__ float g_SKp[NSEG * NB * HEADS * 32];
__device__ float g_A[NB * HEADS * 32 * 32];   // softmaxed attention
__device__ float g_O[(size_t)NB * 128 * HW];  // attn @ v

__constant__ int   c_comp[16] = {0,1,2,3, 1,0,3,2, 2,3,0,1, 3,2,1,0};
__constant__ float c_sign[16] = {1,-1,-1,-1, 1,1,-1,1, 1,1,1,-1, 1,-1,1,1};

// ---------------- Hamilton expansion -> transposed layout ----------------
// Output layout: Wt[(in_full * T + t) * (4*O) + out_full]
__global__ void expand_kernel(const float* __restrict__ br, const float* __restrict__ bi,
                              const float* __restrict__ bj, const float* __restrict__ bk,
                              float* __restrict__ Wt, int O, int I, int T) {
    int idx = blockIdx.x * blockDim.x + threadIdx.x;
    int total = 16 * O * I * T;
    if (idx >= total) return;
    int t   = idx % T;
    int rem = idx / T;
    int inf = rem % (4 * I);
    int of  = rem / (4 * I);
    int p = of / O, o  = of - p * O;
    int q = inf / I, ii = inf - q * I;
    int sel = c_comp[p * 4 + q];
    const float* src = (sel == 0) ? br : (sel == 1) ? bi : (sel == 2) ? bj : bk;
    float v = c_sign[p * 4 + q] * src[(o * I + ii) * T + t];
    Wt[(size_t)(inf * T + t) * (4 * O) + of] = v;
}

// ---------------- 1x1 conv as SGEMM: C[b] = Wt^T @ X[b] + bias ----------------
// Wt is [K][M]. N = HW. 64x64 tile, BK=16, 256 threads, 4x4 microtile.
template<int M, int K>
__global__ __launch_bounds__(256) void gemm1x1_kernel(const float* __restrict__ Wt,
                                                      const float* __restrict__ X,
                                                      const float* __restrict__ bias,
                                                      float* __restrict__ C) {
    const int N = HW;
    __shared__ __align__(16) float Ws[16][64];
    __shared__ __align__(16) float Xs[16][64];
    int b  = blockIdx.z;
    int m0 = blockIdx.y * 64, n0 = blockIdx.x * 64;
    const float* Xb = X + (size_t)b * K * N;
    float* Cb = C + (size_t)b * M * N;
    int tid = threadIdx.x;
    int tx = tid & 15, ty = tid >> 4;
    float acc[4][4];
#pragma unroll
    for (int i = 0; i < 4; i++)
#pragma unroll
        for (int j = 0; j < 4; j++) acc[i][j] = 0.f;

    for (int k0 = 0; k0 < K; k0 += 16) {
        __syncthreads();
        for (int i = tid; i < 1024; i += 256) {
            int kk = i >> 6, m = i & 63;
            Ws[kk][m] = Wt[(size_t)(k0 + kk) * M + m0 + m];
            Xs[kk][m] = Xb[(size_t)(k0 + kk) * N + n0 + m];
        }
        __syncthreads();
#pragma unroll
        for (int kk = 0; kk < 16; kk++) {
            float4 a4 = *(const float4*)&Ws[kk][ty * 4];
            float4 b4 = *(const float4*)&Xs[kk][tx * 4];
            float a[4] = {a4.x, a4.y, a4.z, a4.w};
            float bb[4] = {b4.x, b4.y, b4.z, b4.w};
#pragma unroll
            for (int i = 0; i < 4; i++)
#pragma unroll
                for (int j = 0; j < 4; j++) acc[i][j] += a[i] * bb[j];
        }
    }
#pragma unroll
    for (int i = 0; i < 4; i++) {
        float bi = bias[m0 + ty * 4 + i];
#pragma unroll
        for (int j = 0; j < 4; j++)
            Cb[(size_t)(m0 + ty * 4 + i) * N + n0 + tx * 4 + j] = acc[i][j] + bi;
    }
}

// ---------------- 3x3 dense conv 384->384, pad 1 ----------------
// Block: 64 out channels x 1 output row (128 px). 256 threads: thread = 4co x 8px.
// Loop input channels in chunks of 8; smem: input halo 8x3x132, weights 8x9x64.
__global__ __launch_bounds__(256) void conv3x3_kernel(const float* __restrict__ X,
                                                      const float* __restrict__ Wt,
                                                      const float* __restrict__ bias,
                                                      float* __restrict__ Y) {
    int co0 = blockIdx.x * 64;
    int y   = blockIdx.y;
    int b   = blockIdx.z;
    const float* Xb = X + (size_t)b * CIN3 * HW;
    int tid  = threadIdx.x;
    int co_r = tid >> 4;            // 0..15
    int x0   = (tid & 15) * 8;      // 0..120
    __shared__ __align__(16) float sX[8][3][132];
    __shared__ __align__(16) float sW[8][9][64];
    float acc[4][8];
#pragma unroll
    for (int c = 0; c < 4; c++)
#pragma unroll
        for (int p = 0; p < 8; p++) acc[c][p] = 0.f;

    for (int ci0 = 0; ci0 < CIN3; ci0 += 8) {
        __syncthreads();
        // input halo: sX[ci][ry][xin+1], xin in [-1,128]
        for (int i = tid; i < 3120; i += 256) {
            int ci = i / 390; int r2 = i - ci * 390;
            int ry = r2 / 130; int xx = r2 - ry * 130;
            int xi = xx - 1;   int yi = y + ry - 1;
            float v = 0.f;
            if (xi >= 0 && xi < WW && yi >= 0 && yi < HH)
                v = Xb[(size_t)(ci0 + ci) * HW + yi * WW + xi];
            sX[ci][ry][xx] = v;
        }
        // weights (already [ci][tap][co] in global -> coalesced + conflict-free)
        for (int i = tid; i < 4608; i += 256) {
            int ci = i / 576; int r2 = i - ci * 576;
            int t = r2 >> 6;  int co = r2 & 63;
            sW[ci][t][co] = Wt[(size_t)((ci0 + ci) * 9 + t) * 384 + co0 + co];
        }
        __syncthreads();
#pragma unroll 2
        for (int ci = 0; ci < 8; ci++) {
#pragma unroll
            for (int ky = 0; ky < 3; ky++) {
                float xv[12];
                const float4* xp = (const float4*)&sX[ci][ky][x0];
                *(float4*)&xv[0] = xp[0];
                *(float4*)&xv[4] = xp[1];
                *(float4*)&xv[8] = xp[2];
#pragma unroll
                for (int kx = 0; kx < 3; kx++) {
                    float4 wv = *(const float4*)&sW[ci][ky * 3 + kx][co_r * 4];
                    float wr[4] = {wv.x, wv.y, wv.z, wv.w};
#pragma unroll
                    for (int c = 0; c < 4; c++)
#pragma unroll
                        for (int p = 0; p < 8; p++)
                            acc[c][p] += wr[c] * xv[p + kx];
                }
            }
        }
    }
    float* Yb = Y + ((size_t)b * CIN3 + co0) * HW + y * WW;
#pragma unroll
    for (int c = 0; c < 4; c++) {
        float bi = bias[co0 + co_r * 4 + c];
#pragma unroll
        for (int p = 0; p < 8; p++)
            Yb[(size_t)(co_r * 4 + c) * HW + x0 + p] = acc[c][p] + bi;
    }
}

// ---------------- attention: gram + sumsq partials (deterministic, no atomics) --
__global__ __launch_bounds__(256) void gram_kernel() {
    int seg = blockIdx.x, h = blockIdx.y, b = blockIdx.z;
    const float* Q  = g_Y2 + ((size_t)b * 384 + h * 32) * HW;
    const float* Kp = g_Y2 + ((size_t)b * 384 + 128 + h * 32) * HW;
    __shared__ float sQ[32][65], sK[32][65];
    int tid = threadIdx.x;
    int c  = tid >> 3;
    int d0 = (tid & 7) * 4;
    float p0 = 0, p1 = 0, p2 = 0, p3 = 0, sqa = 0;
    int s0 = seg * 1024;
    for (int cs = 0; cs < 1024; cs += 64) {
        __syncthreads();
        for (int i = tid; i < 2048; i += 256) {
            int cc = i >> 6, ss = i & 63;
            sQ[cc][ss] = Q[(size_t)cc * HW + s0 + cs + ss];
            sK[cc][ss] = Kp[(size_t)cc * HW + s0 + cs + ss];
        }
        __syncthreads();
#pragma unroll 4
        for (int ss = 0; ss < 64; ss++) {
            float qv = sQ[c][ss];
            p0 += qv * sK[d0 + 0][ss];
            p1 += qv * sK[d0 + 1][ss];
            p2 += qv * sK[d0 + 2][ss];
            p3 += qv * sK[d0 + 3][ss];
        }
        if (tid < 32) {
            for (int ss = 0; ss < 64; ss++) { float v = sQ[tid][ss]; sqa += v * v; }
        } else if (tid < 64) {
            for (int ss = 0; ss < 64; ss++) { float v = sK[tid - 32][ss]; sqa += v * v; }
        }
    }
    int bh = b * HEADS + h;
    float* Gp = g_Gp + ((size_t)(seg * NB * HEADS + bh) * 32 + c) * 32;
    Gp[d0 + 0] = p0; Gp[d0 + 1] = p1; Gp[d0 + 2] = p2; Gp[d0 + 3] = p3;
    if (tid < 32)      g_SQp[(seg * NB * HEADS + bh) * 32 + tid] = sqa;
    else if (tid < 64) g_SKp[(seg * NB * HEADS + bh) * 32 + tid - 32] = sqa;
}

// reduce partials, scale by inverse norms * temperature, softmax over d
__global__ void softmax_kernel(const float* __restrict__ temp) {
    int h = blockIdx.x, b = blockIdx.y;
    int bh = b * HEADS + h;
    int tid = threadIdx.x;
    int w = tid >> 5, lane = tid & 31;
    float tpr = temp[h];
    float sk = 0;
    for (int s = 0; s < NSEG; s++) sk += g_SKp[(s * NB * HEADS + bh) * 32 + lane];
    float invk = 1.f / fmaxf(sqrtf(sk), 1e-12f);
    for (int c = w * 4; c < w * 4 + 4; c++) {
        float sq = 0;
        for (int s = 0; s < NSEG; s++) sq += g_SQp[(s * NB * HEADS + bh) * 32 + c];
        float invq = 1.f / fmaxf(sqrtf(sq), 1e-12f);
        float g = 0;
        for (int s = 0; s < NSEG; s++)
            g += g_Gp[((size_t)(s * NB * HEADS + bh) * 32 + c) * 32 + lane];
        float v = g * invq * invk * tpr;
        float mx = v;
        for (int o = 16; o; o >>= 1) mx = fmaxf(mx, __shfl_xor_sync(0xffffffffu, mx, o));
        float e = __expf(v - mx);
        float sum = e;
        for (int o = 16; o; o >>= 1) sum += __shfl_xor_sync(0xffffffffu, sum, o);
        g_A[((size_t)bh * 32 + c) * 32 + lane] = e / sum;
    }
}

// out[b, h*32+c, s] = sum_d A[c][d] * v[d][s]
__global__ __launch_bounds__(256) void attnv_kernel() {
    int h = blockIdx.y, b = blockIdx.z;
    int s = blockIdx.x * 256 + threadIdx.x;
    int bh = b * HEADS + h;
    __shared__ float sA[32][32];
    for (int i = threadIdx.x; i < 1024; i += 256)
        sA[i >> 5][i & 31] = g_A[(size_t)bh * 1024 + i];
    __syncthreads();
    const float* V  = g_Y2 + ((size_t)b * 384 + 256 + h * 32) * HW;
    float* Op = g_O + ((size_t)b * 128 + h * 32) * HW;
    float acc[32];
#pragma unroll
    for (int c = 0; c < 32; c++) acc[c] = 0.f;
#pragma unroll 4
    for (int d = 0; d < 32; d++) {
        float vv = V[(size_t)d * HW + s];
#pragma unroll
        for (int c = 0; c < 32; c++) acc[c] += sA[c][d] * vv;
    }
#pragma unroll
    for (int c = 0; c < 32; c++) Op[(size_t)c * HW + s] = acc[c];
}

// ---------------- launch ----------------
extern "C" void kernel_launch(void* const* d_in, const int* in_sizes, int n_in,
                              void* d_out, int out_size) {
    const float* x     = (const float*)d_in[0];
    const float* qkv_r = (const float*)d_in[1];
    const float* qkv_i = (const float*)d_in[2];
    const float* qkv_j = (const float*)d_in[3];
    const float* qkv_k = (const float*)d_in[4];
    const float* qkv_b = (const float*)d_in[5];
    const float* dw_r  = (const float*)d_in[6];
    const float* dw_i  = (const float*)d_in[7];
    const float* dw_j  = (const float*)d_in[8];
    const float* dw_k  = (const float*)d_in[9];
    const float* dw_b  = (const float*)d_in[10];
    const float* po_r  = (const float*)d_in[11];
    const float* po_i  = (const float*)d_in[12];
    const float* po_j  = (const float*)d_in[13];
    const float* po_k  = (const float*)d_in[14];
    const float* po_b  = (const float*)d_in[15];
    const float* temp  = (const float*)d_in[16];
    float* out = (float*)d_out;

    float *pW1t, *pW2t, *pW3t, *pY1, *pY2, *pO;
    cudaGetSymbolAddress((void**)&pW1t, g_W1t);
    cudaGetSymbolAddress((void**)&pW2t, g_W2t);
    cudaGetSymbolAddress((void**)&pW3t, g_W3t);
    cudaGetSymbolAddress((void**)&pY1, g_Y1);
    cudaGetSymbolAddress((void**)&pY2, g_Y2);
    cudaGetSymbolAddress((void**)&pO,  g_O);

    // weight expansion
    expand_kernel<<<(16 * 96 * 32 + 255) / 256, 256>>>(qkv_r, qkv_i, qkv_j, qkv_k, pW1t, 96, 32, 1);
    expand_kernel<<<(16 * 96 * 96 * 9 + 255) / 256, 256>>>(dw_r, dw_i, dw_j, dw_k, pW2t, 96, 96, 9);
    expand_kernel<<<(16 * 32 * 32 + 255) / 256, 256>>>(po_r, po_i, po_j, po_k, pW3t, 32, 32, 1);

    // qkv 1x1: Y1 = W1 @ x + b
    gemm1x1_kernel<384, 128><<<dim3(256, 6, 2), 256>>>(pW1t, x, qkv_b, pY1);
    // dw 3x3: Y2 = conv3x3(Y1) + b
    conv3x3_kernel<<<dim3(6, 128, 2), 256>>>(pY1, pW2t, dw_b, pY2);
    // channel attention
    gram_kernel<<<dim3(NSEG, HEADS, NB), 256>>>();
    softmax_kernel<<<dim3(HEADS, NB), 256>>>(temp);
    attnv_kernel<<<dim3(HW / 256, HEADS, NB), 256>>>();
    // po 1x1 -> output
    gemm1x1_kernel<128, 128><<<dim3(256, 2, 2), 256>>>(pW3t, pO, po_b, out);
}

// round 7
// speedup vs baseline: 1.0996x; 1.0996x over previous
#include <cuda_runtime.h>
#include <math.h>

// Problem constants
#define HH 128
#define WW 128
#define HW 16384
#define NB 2
#define HEADS 4
#define CIN3 384
#define NSEG 16

typedef unsigned long long u64;

// ---- packed f32x2 helpers (sm_103a FFMA2 path) ----
__device__ __forceinline__ u64 pk2(float lo, float hi) {
    u64 r; asm("mov.b64 %0, {%1, %2};" : "=l"(r) : "f"(lo), "f"(hi)); return r;
}
__device__ __forceinline__ void fma2(u64& d, u64 a, u64 b) {
    asm("fma.rn.f32x2 %0, %1, %2, %0;" : "+l"(d) : "l"(a), "l"(b));
}
__device__ __forceinline__ float2 up2(u64 v) {
    float lo, hi; asm("mov.b64 {%0, %1}, %2;" : "=f"(lo), "=f"(hi) : "l"(v));
    return make_float2(lo, hi);
}

// ---------------- scratch (static device arrays; no allocation) ----------------
__device__ float g_W1t[128 * 384];            // qkv weight, [k][m]
__device__ float g_W2t[384 * 9 * 384];        // dw weight, [ci][tap][co]
__device__ float g_W3t[128 * 128];            // po weight, [k][m]
__device__ float g_Y1[(size_t)NB * 384 * HW]; // after qkv 1x1
__device__ float g_Y2[(size_t)NB * 384 * HW]; // after dw 3x3
__device__ float g_Gp[NSEG * NB * HEADS * 32 * 32]; // gram partials per segment
__device__ float g_SQp[NSEG * NB * HEADS * 32];
__device__ float g_SKp[NSEG * NB * HEADS * 32];
__device__ float g_A[NB * HEADS * 32 * 32];   // softmaxed attention
__device__ float g_O[(size_t)NB * 128 * HW];  // attn @ v

__constant__ int   c_comp[16] = {0,1,2,3, 1,0,3,2, 2,3,0,1, 3,2,1,0};
__constant__ float c_sign[16] = {1,-1,-1,-1, 1,1,-1,1, 1,1,1,-1, 1,-1,1,1};

// ---------------- Hamilton expansion -> transposed layout ----------------
// Output layout: Wt[(in_full * T + t) * (4*O) + out_full]
__global__ void expand_kernel(const float* __restrict__ br, const float* __restrict__ bi,
                              const float* __restrict__ bj, const float* __restrict__ bk,
                              float* __restrict__ Wt, int O, int I, int T) {
    int idx = blockIdx.x * blockDim.x + threadIdx.x;
    int total = 16 * O * I * T;
    if (idx >= total) return;
    int t   = idx % T;
    int rem = idx / T;
    int inf = rem % (4 * I);
    int of  = rem / (4 * I);
    int p = of / O, o  = of - p * O;
    int q = inf / I, ii = inf - q * I;
    int sel = c_comp[p * 4 + q];
    const float* src = (sel == 0) ? br : (sel == 1) ? bi : (sel == 2) ? bj : bk;
    float v = c_sign[p * 4 + q] * src[(o * I + ii) * T + t];
    Wt[(size_t)(inf * T + t) * (4 * O) + of] = v;
}

// ---------------- 1x1 conv as SGEMM: C[b] = Wt^T @ X[b] + bias ----------------
// Wt is [K][M]. N = HW. 64x64 tile, BK=16, 256 threads, 4x4 microtile, FFMA2.
template<int M, int K>
__global__ __launch_bounds__(256) void gemm1x1_kernel(const float* __restrict__ Wt,
                                                      const float* __restrict__ X,
                                                      const float* __restrict__ bias,
                                                      float* __restrict__ C) {
    const int N = HW;
    __shared__ __align__(16) float Ws[16][64];
    __shared__ __align__(16) float Xs[16][64];
    int b  = blockIdx.z;
    int m0 = blockIdx.y * 64, n0 = blockIdx.x * 64;
    const float* Xb = X + (size_t)b * K * N;
    float* Cb = C + (size_t)b * M * N;
    int tid = threadIdx.x;
    int tx = tid & 15, ty = tid >> 4;
    int lkk = tid >> 4, lm4 = (tid & 15) * 4;   // vectorized tile-load coords
    u64 acc2[4][2];
#pragma unroll
    for (int i = 0; i < 4; i++) { acc2[i][0] = 0ull; acc2[i][1] = 0ull; }

    for (int k0 = 0; k0 < K; k0 += 16) {
        __syncthreads();
        *(float4*)&Ws[lkk][lm4] = *(const float4*)&Wt[(size_t)(k0 + lkk) * M + m0 + lm4];
        *(float4*)&Xs[lkk][lm4] = *(const float4*)&Xb[(size_t)(k0 + lkk) * N + n0 + lm4];
        __syncthreads();
#pragma unroll
        for (int kk = 0; kk < 16; kk++) {
            float4 a4 = *(const float4*)&Ws[kk][ty * 4];
            const u64* bp = (const u64*)&Xs[kk][tx * 4];
            u64 b01 = bp[0], b23 = bp[1];
            u64 a0 = pk2(a4.x, a4.x), a1 = pk2(a4.y, a4.y);
            u64 a2 = pk2(a4.z, a4.z), a3 = pk2(a4.w, a4.w);
            fma2(acc2[0][0], a0, b01); fma2(acc2[0][1], a0, b23);
            fma2(acc2[1][0], a1, b01); fma2(acc2[1][1], a1, b23);
            fma2(acc2[2][0], a2, b01); fma2(acc2[2][1], a2, b23);
            fma2(acc2[3][0], a3, b01); fma2(acc2[3][1], a3, b23);
        }
    }
#pragma unroll
    for (int i = 0; i < 4; i++) {
        float bi = bias[m0 + ty * 4 + i];
        float2 lo = up2(acc2[i][0]), hi = up2(acc2[i][1]);
        float4 o = make_float4(lo.x + bi, lo.y + bi, hi.x + bi, hi.y + bi);
        *(float4*)&Cb[(size_t)(m0 + ty * 4 + i) * N + n0 + tx * 4] = o;
    }
}

// ---------------- 3x3 dense conv 384->384, pad 1, FFMA2 on co-pairs ----------------
// Block: 64 out channels x 1 output row (128 px). 256 threads: thread = 4co x 8px.
// f32x2 lanes carry (co, co+1); weight pairs come pre-packed from smem via LDS.64.
__global__ __launch_bounds__(256) void conv3x3_kernel(const float* __restrict__ X,
                                                      const float* __restrict__ Wt,
                                                      const float* __restrict__ bias,
                                                      float* __restrict__ Y) {
    int co0 = blockIdx.x * 64;
    int y   = blockIdx.y;
    int b   = blockIdx.z;
    const float* Xb = X + (size_t)b * CIN3 * HW;
    int tid  = threadIdx.x;
    int co_r = tid >> 4;            // 0..15
    int x0   = (tid & 15) * 8;      // 0..120
    __shared__ __align__(16) float sX[8][3][132];
    __shared__ __align__(16) float sW[8][9][64];
    u64 acc2[2][8];                 // [co-pair (0:co+0/1, 1:co+2/3)][pixel]
#pragma unroll
    for (int cp = 0; cp < 2; cp++)
#pragma unroll
        for (int p = 0; p < 8; p++) acc2[cp][p] = 0ull;

    for (int ci0 = 0; ci0 < CIN3; ci0 += 8) {
        __syncthreads();
        // input halo: sX[ci][ry][xin+1], xin in [-1,128]
        for (int i = tid; i < 3120; i += 256) {
            int ci = i / 390; int r2 = i - ci * 390;
            int ry = r2 / 130; int xx = r2 - ry * 130;
            int xi = xx - 1;   int yi = y + ry - 1;
            float v = 0.f;
            if (xi >= 0 && xi < WW && yi >= 0 && yi < HH)
                v = Xb[(size_t)(ci0 + ci) * HW + yi * WW + xi];
            sX[ci][ry][xx] = v;
        }
        // weights ([ci][tap][co] in global -> coalesced, conflict-free)
        for (int i = tid; i < 4608; i += 256) {
            int ci = i / 576; int r2 = i - ci * 576;
            int t = r2 >> 6;  int co = r2 & 63;
            sW[ci][t][co] = Wt[(size_t)((ci0 + ci) * 9 + t) * 384 + co0 + co];
        }
        __syncthreads();
#pragma unroll 2
        for (int ci = 0; ci < 8; ci++) {
#pragma unroll
            for (int ky = 0; ky < 3; ky++) {
                float xv[12];
                const float4* xp = (const float4*)&sX[ci][ky][x0];
                *(float4*)&xv[0] = xp[0];
                *(float4*)&xv[4] = xp[1];
                *(float4*)&xv[8] = xp[2];
                u64 xd[10];
#pragma unroll
                for (int p = 0; p < 10; p++) xd[p] = pk2(xv[p], xv[p]);
#pragma unroll
                for (int kx = 0; kx < 3; kx++) {
                    const u64* wrow = (const u64*)&sW[ci][ky * 3 + kx][co_r * 4];
                    u64 w01 = wrow[0], w23 = wrow[1];
#pragma unroll
                    for (int p = 0; p < 8; p++) {
                        fma2(acc2[0][p], xd[p + kx], w01);
                        fma2(acc2[1][p], xd[p + kx], w23);
                    }
                }
            }
        }
    }
    // unpack: acc2[cp][p] lanes = channels co_r*4 + 2*cp + {0,1}
    float outv[4][8];
#pragma unroll
    for (int p = 0; p < 8; p++) {
        float2 a = up2(acc2[0][p]); outv[0][p] = a.x; outv[1][p] = a.y;
        float2 c = up2(acc2[1][p]); outv[2][p] = c.x; outv[3][p] = c.y;
    }
    float* Yb = Y + ((size_t)b * CIN3 + co0) * HW + y * WW;
#pragma unroll
    for (int c = 0; c < 4; c++) {
        float bi = bias[co0 + co_r * 4 + c];
        float4 lo = make_float4(outv[c][0] + bi, outv[c][1] + bi, outv[c][2] + bi, outv[c][3] + bi);
        float4 hi = make_float4(outv[c][4] + bi, outv[c][5] + bi, outv[c][6] + bi, outv[c][7] + bi);
        float* row = &Yb[(size_t)(co_r * 4 + c) * HW + x0];
        *(float4*)&row[0] = lo;
        *(float4*)&row[4] = hi;
    }
}

// ---------------- attention: gram + sumsq partials (deterministic, no atomics) --
__global__ __launch_bounds__(256) void gram_kernel() {
    int seg = blockIdx.x, h = blockIdx.y, b = blockIdx.z;
    const float* Q  = g_Y2 + ((size_t)b * 384 + h * 32) * HW;
    const float* Kp = g_Y2 + ((size_t)b * 384 + 128 + h * 32) * HW;
    __shared__ float sQ[32][65], sK[32][65];
    int tid = threadIdx.x;
    int c  = tid >> 3;
    int d0 = (tid & 7) * 4;
    float p0 = 0, p1 = 0, p2 = 0, p3 = 0, sqa = 0;
    int s0 = seg * 1024;
    for (int cs = 0; cs < 1024; cs += 64) {
        __syncthreads();
        for (int i = tid; i < 2048; i += 256) {
            int cc = i >> 6, ss = i & 63;
            sQ[cc][ss] = Q[(size_t)cc * HW + s0 + cs + ss];
            sK[cc][ss] = Kp[(size_t)cc * HW + s0 + cs + ss];
        }
        __syncthreads();
#pragma unroll 4
        for (int ss = 0; ss < 64; ss++) {
            float qv = sQ[c][ss];
            p0 += qv * sK[d0 + 0][ss];
            p1 += qv * sK[d0 + 1][ss];
            p2 += qv * sK[d0 + 2][ss];
            p3 += qv * sK[d0 + 3][ss];
        }
        if (tid < 32) {
            for (int ss = 0; ss < 64; ss++) { float v = sQ[tid][ss]; sqa += v * v; }
        } else if (tid < 64) {
            for (int ss = 0; ss < 64; ss++) { float v = sK[tid - 32][ss]; sqa += v * v; }
        }
    }
    int bh = b * HEADS + h;
    float* Gp = g_Gp + ((size_t)(seg * NB * HEADS + bh) * 32 + c) * 32;
    Gp[d0 + 0] = p0; Gp[d0 + 1] = p1; Gp[d0 + 2] = p2; Gp[d0 + 3] = p3;
    if (tid < 32)      g_SQp[(seg * NB * HEADS + bh) * 32 + tid] = sqa;
    else if (tid < 64) g_SKp[(seg * NB * HEADS + bh) * 32 + tid - 32] = sqa;
}

// reduce partials, scale by inverse norms * temperature, softmax over d
__global__ void softmax_kernel(const float* __restrict__ temp) {
    int h = blockIdx.x, b = blockIdx.y;
    int bh = b * HEADS + h;
    int tid = threadIdx.x;
    int w = tid >> 5, lane = tid & 31;
    float tpr = temp[h];
    float sk = 0;
    for (int s = 0; s < NSEG; s++) sk += g_SKp[(s * NB * HEADS + bh) * 32 + lane];
    float invk = 1.f / fmaxf(sqrtf(sk), 1e-12f);
    for (int c = w * 4; c < w * 4 + 4; c++) {
        float sq = 0;
        for (int s = 0; s < NSEG; s++) sq += g_SQp[(s * NB * HEADS + bh) * 32 + c];
        float invq = 1.f / fmaxf(sqrtf(sq), 1e-12f);
        float g = 0;
        for (int s = 0; s < NSEG; s++)
            g += g_Gp[((size_t)(s * NB * HEADS + bh) * 32 + c) * 32 + lane];
        float v = g * invq * invk * tpr;
        float mx = v;
        for (int o = 16; o; o >>= 1) mx = fmaxf(mx, __shfl_xor_sync(0xffffffffu, mx, o));
        float e = __expf(v - mx);
        float sum = e;
        for (int o = 16; o; o >>= 1) sum += __shfl_xor_sync(0xffffffffu, sum, o);
        g_A[((size_t)bh * 32 + c) * 32 + lane] = e / sum;
    }
}

// out[b, h*32+c, s] = sum_d A[c][d] * v[d][s]
__global__ __launch_bounds__(256) void attnv_kernel() {
    int h = blockIdx.y, b = blockIdx.z;
    int s = blockIdx.x * 256 + threadIdx.x;
    int bh = b * HEADS + h;
    __shared__ float sA[32][32];
    for (int i = threadIdx.x; i < 1024; i += 256)
        sA[i >> 5][i & 31] = g_A[(size_t)bh * 1024 + i];
    __syncthreads();
    const float* V  = g_Y2 + ((size_t)b * 384 + 256 + h * 32) * HW;
    float* Op = g_O + ((size_t)b * 128 + h * 32) * HW;
    float acc[32];
#pragma unroll
    for (int c = 0; c < 32; c++) acc[c] = 0.f;
#pragma unroll 4
    for (int d = 0; d < 32; d++) {
        float vv = V[(size_t)d * HW + s];
#pragma unroll
        for (int c = 0; c < 32; c++) acc[c] += sA[c][d] * vv;
    }
#pragma unroll
    for (int c = 0; c < 32; c++) Op[(size_t)c * HW + s] = acc[c];
}

// ---------------- launch ----------------
extern "C" void kernel_launch(void* const* d_in, const int* in_sizes, int n_in,
                              void* d_out, int out_size) {
    const float* x     = (const float*)d_in[0];
    const float* qkv_r = (const float*)d_in[1];
    const float* qkv_i = (const float*)d_in[2];
    const float* qkv_j = (const float*)d_in[3];
    const float* qkv_k = (const float*)d_in[4];
    const float* qkv_b = (const float*)d_in[5];
    const float* dw_r  = (const float*)d_in[6];
    const float* dw_i  = (const float*)d_in[7];
    const float* dw_j  = (const float*)d_in[8];
    const float* dw_k  = (const float*)d_in[9];
    const float* dw_b  = (const float*)d_in[10];
    const float* po_r  = (const float*)d_in[11];
    const float* po_i  = (const float*)d_in[12];
    const float* po_j  = (const float*)d_in[13];
    const float* po_k  = (const float*)d_in[14];
    const float* po_b  = (const float*)d_in[15];
    const float* temp  = (const float*)d_in[16];
    float* out = (float*)d_out;

    float *pW1t, *pW2t, *pW3t, *pY1, *pY2, *pO;
    cudaGetSymbolAddress((void**)&pW1t, g_W1t);
    cudaGetSymbolAddress((void**)&pW2t, g_W2t);
    cudaGetSymbolAddress((void**)&pW3t, g_W3t);
    cudaGetSymbolAddress((void**)&pY1, g_Y1);
    cudaGetSymbolAddress((void**)&pY2, g_Y2);
    cudaGetSymbolAddress((void**)&pO,  g_O);

    // weight expansion
    expand_kernel<<<(16 * 96 * 32 + 255) / 256, 256>>>(qkv_r, qkv_i, qkv_j, qkv_k, pW1t, 96, 32, 1);
    expand_kernel<<<(16 * 96 * 96 * 9 + 255) / 256, 256>>>(dw_r, dw_i, dw_j, dw_k, pW2t, 96, 96, 9);
    expand_kernel<<<(16 * 32 * 32 + 255) / 256, 256>>>(po_r, po_i, po_j, po_k, pW3t, 32, 32, 1);

    // qkv 1x1: Y1 = W1 @ x + b
    gemm1x1_kernel<384, 128><<<dim3(256, 6, 2), 256>>>(pW1t, x, qkv_b, pY1);
    // dw 3x3: Y2 = conv3x3(Y1) + b
    conv3x3_kernel<<<dim3(6, 128, 2), 256>>>(pY1, pW2t, dw_b, pY2);
    // channel attention
    gram_kernel<<<dim3(NSEG, HEADS, NB), 256>>>();
    softmax_kernel<<<dim3(HEADS, NB), 256>>>(temp);
    attnv_kernel<<<dim3(HW / 256, HEADS, NB), 256>>>();
    // po 1x1 -> output
    gemm1x1_kernel<128, 128><<<dim3(256, 2, 2), 256>>>(pW3t, pO, po_b, out);
}